// round 2
// baseline (speedup 1.0000x reference)
#include <cuda_runtime.h>
#include <stdint.h>
#include <math.h>

// Problem constants
#define T_   4096
#define D_   128
#define H_   512
#define H3_  1536
#define E_   256
#define WN_  4
#define V_   50000

#define GC   128      // CTAs in sequential kernel (<=148 SMs -> all co-resident)
#define NT   256      // threads per CTA

// ---------------- device scratch (static: no runtime allocation) ----------------
__device__ float    g_XW [T_ * H3_];          //  25 MB : x@W + b
__device__ float    g_XWa[T_ * H_];           //   8 MB : x@Wa + ba
__device__ float    g_GWx[T_ * WN_ * H3_];    // 100 MB : emb[wid]@Ww + bw
__device__ float    g_cw [WN_ * H_];          // per-step c_w broadcast (active-compact)
__device__ int      g_meta[T_];               // packed: nact | active word ids
__device__ unsigned g_bar;                    // monotonic grid-barrier counter
__device__ int      g_flags;                  // mask dtype detector flags

// ---------------- mask dtype detection ----------------
// word_mask is a jax bool; the harness may hand it over as int32, float32 or
// uint8. Classify from bit patterns of the first 4096 32-bit words (16 KB --
// exactly the uint8 buffer size, within bounds for all candidates).
__global__ void k_detect_init() { g_flags = 7; g_bar = 0; }

__global__ void k_detect(const unsigned* __restrict__ m) {
    int i = blockIdx.x * blockDim.x + threadIdx.x;
    if (i >= 4096) return;
    unsigned w = m[i];
    int bad = 0;
    if (w > 1u)                          bad |= 1;   // not int32 0/1
    if (w != 0u && w != 0x3F800000u)     bad |= 2;   // not float32 0/1
    if ((w & 0xFEFEFEFEu) != 0u)         bad |= 4;   // not uint8 0/1
    if (bad) atomicAnd(&g_flags, ~bad);
}

__device__ __forceinline__ int read_mask(const void* p, int i, int mode) {
    if (mode == 0) return ((const int*)p)[i] != 0;
    if (mode == 1) return ((const float*)p)[i] != 0.0f;
    return ((const unsigned char*)p)[i] != 0;
}

// ---------------- per-step metadata: active word list ----------------
__global__ void k_meta(const void* __restrict__ mask) {
    int t = blockIdx.x * blockDim.x + threadIdx.x;
    if (t >= T_) return;
    int flags = g_flags;
    int mode = (flags & 1) ? 0 : ((flags & 2) ? 1 : 2);
    int nact = 0, ws[4] = {0, 0, 0, 0};
    #pragma unroll
    for (int w = 0; w < WN_; ++w) {
        if (read_mask(mask, t * WN_ + w, mode)) ws[nact++] = w;
    }
    g_meta[t] = nact | (ws[0] << 4) | (ws[1] << 6) | (ws[2] << 8) | (ws[3] << 10);
}

// ---------------- precompute GEMM ----------------
// C[M,N] = gather(A)[M,K] @ B[K,N] + bias.  BM=128, BN=64, BK=16, 256 thr, 8x4 tile.
// M%128==0, N%64==0, K%16==0 for all three uses.
__global__ __launch_bounds__(256) void k_gemm(
    const float* __restrict__ A, const int* __restrict__ gidx,
    const float* __restrict__ B, const float* __restrict__ bias,
    int M, int N, int K, int sel)
{
    float* C = (sel == 0) ? g_XW : (sel == 1) ? g_XWa : g_GWx;

    __shared__ float As[16 * 130];   // [k][m], pitch 130 to kill store conflicts
    __shared__ float Bs[16 * 64];    // [k][n]

    int tid = threadIdx.x;
    int bm = blockIdx.y * 128, bn = blockIdx.x * 64;
    int tx = tid & 15;        // n
    int ty = tid >> 4;        // m

    float acc[8][4];
    #pragma unroll
    for (int i = 0; i < 8; ++i)
        #pragma unroll
        for (int j = 0; j < 4; ++j) acc[i][j] = 0.0f;

    for (int k0 = 0; k0 < K; k0 += 16) {
        // A tile: 128 rows x 16 k = 512 float4, 2 per thread
        #pragma unroll
        for (int i = 0; i < 2; ++i) {
            int f = tid + i * 256;
            int row = f >> 2, kq = (f & 3) * 4;
            int ar = gidx ? gidx[bm + row] : (bm + row);
            float4 v = *(const float4*)(A + (size_t)ar * K + k0 + kq);
            As[(kq + 0) * 130 + row] = v.x;
            As[(kq + 1) * 130 + row] = v.y;
            As[(kq + 2) * 130 + row] = v.z;
            As[(kq + 3) * 130 + row] = v.w;
        }
        // B tile: 16 rows x 64 cols = 256 float4, 1 per thread
        {
            int row = tid >> 4, cq = (tid & 15) * 4;
            float4 v = *(const float4*)(B + (size_t)(k0 + row) * N + bn + cq);
            *(float4*)&Bs[row * 64 + cq] = v;
        }
        __syncthreads();
        #pragma unroll
        for (int kk = 0; kk < 16; ++kk) {
            float a[8], b[4];
            #pragma unroll
            for (int i = 0; i < 8; ++i) a[i] = As[kk * 130 + ty + i * 16];
            #pragma unroll
            for (int j = 0; j < 4; ++j) b[j] = Bs[kk * 64 + tx + j * 16];
            #pragma unroll
            for (int i = 0; i < 8; ++i)
                #pragma unroll
                for (int j = 0; j < 4; ++j) acc[i][j] += a[i] * b[j];
        }
        __syncthreads();
    }
    #pragma unroll
    for (int i = 0; i < 8; ++i) {
        int m = bm + ty + i * 16;
        #pragma unroll
        for (int j = 0; j < 4; ++j) {
            int n = bn + tx + j * 16;
            C[(size_t)m * N + n] = acc[i][j] + bias[n];
        }
    }
}

// ---------------- grid barrier (monotonic counter) ----------------
__device__ __forceinline__ void gridbar(unsigned target) {
    __syncthreads();
    if (threadIdx.x == 0) {
        __threadfence();
        atomicAdd(&g_bar, 1u);
        volatile unsigned* p = &g_bar;
        while (*p < target) { }
        __threadfence();
    }
    __syncthreads();
}

// ---------------- persistent sequential kernel ----------------
// smem layout (floats):
#define SM_U    0                      // 12 * 520  (U cols:  gate*4+jl)
#define SM_UW   (SM_U + 12 * 520)      // 12 * 520  (Uw cols)
#define SM_UA   (SM_UW + 12 * 520)     //  4 * 520  (Ua cols)
#define SM_HS   (SM_UA + 4 * 520)      //  4 * 512  (active-word h states)
#define SM_CS   (SM_HS + 4 * 512)      //  4 * 512  (active-word c states)
#define SM_CW   (SM_CS + 4 * 512)      //  4 * 512  (full c_w rows)
#define SM_HP   (SM_CW + 4 * 512)      //  512      (h_prev)
#define SM_RA   (SM_HP + 512)          //  48       (phase-A dot results)
#define SM_RB   (SM_RA + 48)           //  12       (gate dot results)
#define SM_RAL  (SM_RB + 16)           //  16       (alpha dot results)
#define SM_TOTF (SM_RAL + 16)
#define SMEM_BYTES (SM_TOTF * 4)

__global__ __launch_bounds__(NT, 1) void k_seq(
    float* __restrict__ out,                 // [T, 1024] = hidden|cell
    const float* __restrict__ U,             // [512, 1536]
    const float* __restrict__ Uw,            // [512, 1536]
    const float* __restrict__ Ua,            // [512, 512]
    const float* __restrict__ h0,
    const float* __restrict__ c0,
    const int*   __restrict__ wstarts)       // [T, 4]
{
    extern __shared__ float sm[];
    const int c   = blockIdx.x;
    const int tid = threadIdx.x;
    const int jbase = 4 * c;
    const int warp = tid >> 5, lane = tid & 31;

    // ---- load weight column slices into smem (one-time per launch) ----
    // col(gate, jl) = gate*512 + jbase + jl ; stored at [gate*4+jl][k], pitch 520
    for (int idx = tid; idx < 3 * 512; idx += NT) {
        int gate = idx >> 9, k = idx & 511;
        const float* pU  = U  + (size_t)k * H3_ + gate * 512 + jbase;
        const float* pUw = Uw + (size_t)k * H3_ + gate * 512 + jbase;
        float4 vU  = *(const float4*)pU;
        float4 vUw = *(const float4*)pUw;
        int b = gate * 4;
        sm[SM_U  + (b + 0) * 520 + k] = vU.x;  sm[SM_U  + (b + 1) * 520 + k] = vU.y;
        sm[SM_U  + (b + 2) * 520 + k] = vU.z;  sm[SM_U  + (b + 3) * 520 + k] = vU.w;
        sm[SM_UW + (b + 0) * 520 + k] = vUw.x; sm[SM_UW + (b + 1) * 520 + k] = vUw.y;
        sm[SM_UW + (b + 2) * 520 + k] = vUw.z; sm[SM_UW + (b + 3) * 520 + k] = vUw.w;
    }
    for (int k = tid; k < 512; k += NT) {
        float4 v = *(const float4*)(Ua + (size_t)k * H_ + jbase);
        sm[SM_UA + 0 * 520 + k] = v.x; sm[SM_UA + 1 * 520 + k] = v.y;
        sm[SM_UA + 2 * 520 + k] = v.z; sm[SM_UA + 3 * 520 + k] = v.w;
    }
    __syncthreads();

    unsigned bcount = 0;

    for (int t = 0; t < T_; ++t) {
        const int meta = g_meta[t];
        const int nact = meta & 7;

        // stage h_prev (512 floats)
        {
            const float* src = t ? (out + (size_t)(t - 1) * 1024) : h0;
            for (int q = tid; q < 128; q += NT)
                ((float4*)(sm + SM_HP))[q] = ((const float4*)src)[q];
        }
        // stage h_s, c_s for active words
        if (nact) {
            for (int q = tid; q < nact * 128; q += NT) {
                int wi = q >> 7, k4 = q & 127;
                int w = (meta >> (4 + 2 * wi)) & 3;
                int s = wstarts[t * WN_ + w];
                const float4* src = (const float4*)(out + (size_t)s * 1024);
                ((float4*)(sm + SM_HS + wi * 512))[k4] = src[k4];
                ((float4*)(sm + SM_CS + wi * 512))[k4] = src[128 + k4];
            }
        }
        __syncthreads();

        if (nact) {
            // ---- phase A: gw dots  (nact*12 dots of length 512) ----
            int ndots = nact * 12;
            for (int d = warp; d < ndots; d += 8) {
                int wi = d / 12, g = d % 12;
                const float4* wt = (const float4*)(sm + SM_UW + g * 520);
                const float4* hv = (const float4*)(sm + SM_HS + wi * 512);
                float acc = 0.0f;
                #pragma unroll
                for (int i = 0; i < 4; ++i) {
                    int k4 = i * 32 + lane;
                    float4 a = wt[k4]; float4 b = hv[k4];
                    acc += a.x * b.x + a.y * b.y + a.z * b.z + a.w * b.w;
                }
                #pragma unroll
                for (int off = 16; off > 0; off >>= 1)
                    acc += __shfl_xor_sync(0xFFFFFFFFu, acc, off);
                if (lane == 0) {
                    int w = (meta >> (4 + 2 * wi)) & 3;
                    int gate = g >> 2, jl = g & 3;
                    sm[SM_RA + d] = acc +
                        g_GWx[((size_t)t * WN_ + w) * H3_ + gate * 512 + jbase + jl];
                }
            }
            __syncthreads();
            // ---- c_w combine: word gates split f | i | g ----
            if (tid < nact * 4) {
                int wi = tid >> 2, jl = tid & 3;
                float f  = sm[SM_RA + wi * 12 + 0 + jl];
                float iw = sm[SM_RA + wi * 12 + 4 + jl];
                float gw = sm[SM_RA + wi * 12 + 8 + jl];
                float cs = sm[SM_CS + wi * 512 + jbase + jl];
                float sf = 1.0f / (1.0f + expf(-f));
                float si = 1.0f / (1.0f + expf(-iw));
                float cw = sf * cs + si * tanhf(gw);
                g_cw[wi * H_ + jbase + jl] = cw;
            }
            gridbar(++bcount * GC);   // publish c_w
            // stage full c_w rows
            for (int q = tid; q < nact * 128; q += NT)
                ((float4*)(sm + SM_CW))[q] = ((const float4*)g_cw)[q];
            __syncthreads();
        }

        // ---- phase B dots: 12 gate dots + nact*4 alpha dots ----
        {
            int ndots = 12 + nact * 4;
            for (int d = warp; d < ndots; d += 8) {
                const float4 *wt, *hv;
                if (d < 12) {
                    wt = (const float4*)(sm + SM_U + d * 520);
                    hv = (const float4*)(sm + SM_HP);
                } else {
                    int a = d - 12; int wi = a >> 2, jl = a & 3;
                    wt = (const float4*)(sm + SM_UA + jl * 520);
                    hv = (const float4*)(sm + SM_CW + wi * 512);
                }
                float acc = 0.0f;
                #pragma unroll
                for (int i = 0; i < 4; ++i) {
                    int k4 = i * 32 + lane;
                    float4 a = wt[k4]; float4 b = hv[k4];
                    acc += a.x * b.x + a.y * b.y + a.z * b.z + a.w * b.w;
                }
                #pragma unroll
                for (int off = 16; off > 0; off >>= 1)
                    acc += __shfl_xor_sync(0xFFFFFFFFu, acc, off);
                if (lane == 0) {
                    if (d < 12) {
                        int gate = d >> 2, jl = d & 3;
                        sm[SM_RB + d] = acc +
                            g_XW[(size_t)t * H3_ + gate * 512 + jbase + jl];
                    } else {
                        int a = d - 12; int jl = a & 3;
                        sm[SM_RAL + a] = acc + g_XWa[(size_t)t * H_ + jbase + jl];
                    }
                }
            }
        }
        __syncthreads();

        // ---- final combine (main gates split i | o | g) ----
        if (tid < 4) {
            int jl = tid, j = jbase + jl;
            float ig = 1.0f / (1.0f + expf(-sm[SM_RB + 0 + jl]));
            float og = 1.0f / (1.0f + expf(-sm[SM_RB + 4 + jl]));
            float gg = tanhf(sm[SM_RB + 8 + jl]);
            float c1;
            if (nact) {
                float e0  = expf(ig);
                float den = e0, num = e0 * gg;
                for (int wi = 0; wi < nact; ++wi) {
                    float a  = 1.0f / (1.0f + expf(-sm[SM_RAL + wi * 4 + jl]));
                    float ea = expf(a);
                    den += ea;
                    num += ea * sm[SM_CW + wi * 512 + j];
                }
                c1 = num / den;
            } else {
                float cp = t ? out[(size_t)(t - 1) * 1024 + 512 + j] : c0[j];
                c1 = (1.0f - ig) * cp + ig * gg;
            }
            float h1 = og * tanhf(c1);
            out[(size_t)t * 1024 + j]       = h1;
            out[(size_t)t * 1024 + 512 + j] = c1;
        }
        gridbar(++bcount * GC);   // publish h_t, c_t
    }
}

// ---------------- launch ----------------
extern "C" void kernel_launch(void* const* d_in, const int* in_sizes, int n_in,
                              void* d_out, int out_size) {
    const float* x        = (const float*)d_in[0];
    const int*   word_ids = (const int*)  d_in[1];
    const int*   wstarts  = (const int*)  d_in[2];
    const void*  wmask    = (const void*) d_in[3];
    const float* h0       = (const float*)d_in[4];
    const float* c0       = (const float*)d_in[5];
    const float* emb      = (const float*)d_in[6];
    const float* W        = (const float*)d_in[7];
    const float* U        = (const float*)d_in[8];
    const float* b        = (const float*)d_in[9];
    const float* Wa       = (const float*)d_in[10];
    const float* Ua       = (const float*)d_in[11];
    const float* ba       = (const float*)d_in[12];
    const float* Ww       = (const float*)d_in[13];
    const float* Uw       = (const float*)d_in[14];
    const float* bw       = (const float*)d_in[15];
    float* out = (float*)d_out;

    // detector + metadata + barrier reset
    k_detect_init<<<1, 1>>>();
    k_detect<<<16, 256>>>((const unsigned*)wmask);
    k_meta<<<16, 256>>>(wmask);

    // precompute GEMMs
    {
        dim3 g0(H3_ / 64, T_ / 128);
        k_gemm<<<g0, 256>>>(x, nullptr, W, b, T_, H3_, D_, 0);
        dim3 g1(H_ / 64, T_ / 128);
        k_gemm<<<g1, 256>>>(x, nullptr, Wa, ba, T_, H_, D_, 1);
        dim3 g2(H3_ / 64, (T_ * WN_) / 128);
        k_gemm<<<g2, 256>>>(emb, word_ids, Ww, bw, T_ * WN_, H3_, E_, 2);
    }

    // persistent sequential kernel
    static_assert(SMEM_BYTES < 227 * 1024, "smem");
    cudaFuncSetAttribute(k_seq, cudaFuncAttributeMaxDynamicSharedMemorySize,
                         SMEM_BYTES);
    k_seq<<<GC, NT, SMEM_BYTES>>>(out, U, Uw, Ua, h0, c0, wstarts);
}

// round 3
// speedup vs baseline: 1.2119x; 1.2119x over previous
#include <cuda_runtime.h>
#include <stdint.h>
#include <math.h>

// Problem constants
#define T_   4096
#define D_   128
#define H_   512
#define H3_  1536
#define E_   256
#define WN_  4

#define GC   128      // CTAs in sequential kernel (<=148 SMs -> all co-resident)
#define NT   256      // threads per CTA

// ---------------- device scratch (static: no runtime allocation) ----------------
__device__ float    g_XW [T_ * H3_];          //  25 MB : x@W + b
__device__ float    g_XWa[T_ * H_];           //   8 MB : x@Wa + ba
__device__ float    g_GWx[T_ * WN_ * H3_];    // 100 MB : emb[wid]@Ww + bw
__device__ float    g_cw [WN_ * H_];          // per-step c_w broadcast (active-compact)
__device__ unsigned g_meta[T_];               // nact(3b) + [w(2b)+d(5b)] x4
__device__ unsigned g_flag[GC * 32];          // per-CTA barrier flags, 128B apart
__device__ int      g_flags;                  // mask dtype detector flags

// ---------------- acquire/release flag ops (NO membar.gl -> no L1 IVALL) ----------
__device__ __forceinline__ unsigned ld_acq(const unsigned* p) {
    unsigned v;
    asm volatile("ld.acquire.gpu.global.u32 %0, [%1];" : "=r"(v) : "l"(p) : "memory");
    return v;
}
__device__ __forceinline__ void st_rel(unsigned* p, unsigned v) {
    asm volatile("st.release.gpu.global.u32 [%0], %1;" :: "l"(p), "r"(v) : "memory");
}

// ---------------- init + mask dtype detection ----------------
__global__ void k_init() {
    if (threadIdx.x == 0) g_flags = 7;
    for (int i = threadIdx.x; i < GC * 32; i += blockDim.x) g_flag[i] = 0;
}

__global__ void k_detect(const unsigned* __restrict__ m) {
    int i = blockIdx.x * blockDim.x + threadIdx.x;
    if (i >= 4096) return;
    unsigned w = m[i];
    int bad = 0;
    if (w > 1u)                          bad |= 1;   // not int32 0/1
    if (w != 0u && w != 0x3F800000u)     bad |= 2;   // not float32 0/1
    if ((w & 0xFEFEFEFEu) != 0u)         bad |= 4;   // not uint8 0/1
    if (bad) atomicAnd(&g_flags, ~bad);
}

__device__ __forceinline__ int read_mask(const void* p, int i, int mode) {
    if (mode == 0) return ((const int*)p)[i] != 0;
    if (mode == 1) return ((const float*)p)[i] != 0.0f;
    return ((const unsigned char*)p)[i] != 0;
}

// ---------------- per-step metadata ----------------
// Active word list, start encoded as offset d = t - start (in [1,5] for real data).
__global__ void k_meta(const void* __restrict__ mask, const int* __restrict__ wstarts) {
    int t = blockIdx.x * blockDim.x + threadIdx.x;
    if (t >= T_) return;
    int flags = g_flags;
    int mode = (flags & 1) ? 0 : ((flags & 2) ? 1 : 2);
    unsigned m = 0;
    int nact = 0;
    #pragma unroll
    for (int w = 0; w < WN_; ++w) {
        if (read_mask(mask, t * WN_ + w, mode)) {
            int d = t - wstarts[t * WN_ + w];
            if (d < 1) d = 1;
            if (d > 31) d = 31;
            m |= (unsigned)(w | (d << 2)) << (3 + 7 * nact);
            ++nact;
        }
    }
    g_meta[t] = m | (unsigned)nact;
}

// ---------------- precompute GEMM ----------------
// C[M,N] = gather(A)[M,K] @ B[K,N] + bias.  BM=128, BN=64, BK=16, 256 thr, 8x4 tile.
__global__ __launch_bounds__(256) void k_gemm(
    const float* __restrict__ A, const int* __restrict__ gidx,
    const float* __restrict__ B, const float* __restrict__ bias,
    int M, int N, int K, int sel)
{
    float* C = (sel == 0) ? g_XW : (sel == 1) ? g_XWa : g_GWx;

    __shared__ float As[16 * 130];
    __shared__ float Bs[16 * 64];

    int tid = threadIdx.x;
    int bm = blockIdx.y * 128, bn = blockIdx.x * 64;
    int tx = tid & 15;
    int ty = tid >> 4;

    float acc[8][4];
    #pragma unroll
    for (int i = 0; i < 8; ++i)
        #pragma unroll
        for (int j = 0; j < 4; ++j) acc[i][j] = 0.0f;

    for (int k0 = 0; k0 < K; k0 += 16) {
        #pragma unroll
        for (int i = 0; i < 2; ++i) {
            int f = tid + i * 256;
            int row = f >> 2, kq = (f & 3) * 4;
            int ar = gidx ? gidx[bm + row] : (bm + row);
            float4 v = *(const float4*)(A + (size_t)ar * K + k0 + kq);
            As[(kq + 0) * 130 + row] = v.x;
            As[(kq + 1) * 130 + row] = v.y;
            As[(kq + 2) * 130 + row] = v.z;
            As[(kq + 3) * 130 + row] = v.w;
        }
        {
            int row = tid >> 4, cq = (tid & 15) * 4;
            float4 v = *(const float4*)(B + (size_t)(k0 + row) * N + bn + cq);
            *(float4*)&Bs[row * 64 + cq] = v;
        }
        __syncthreads();
        #pragma unroll
        for (int kk = 0; kk < 16; ++kk) {
            float a[8], b[4];
            #pragma unroll
            for (int i = 0; i < 8; ++i) a[i] = As[kk * 130 + ty + i * 16];
            #pragma unroll
            for (int j = 0; j < 4; ++j) b[j] = Bs[kk * 64 + tx + j * 16];
            #pragma unroll
            for (int i = 0; i < 8; ++i)
                #pragma unroll
                for (int j = 0; j < 4; ++j) acc[i][j] += a[i] * b[j];
        }
        __syncthreads();
    }
    #pragma unroll
    for (int i = 0; i < 8; ++i) {
        int m = bm + ty + i * 16;
        #pragma unroll
        for (int j = 0; j < 4; ++j) {
            int n = bn + tx + j * 16;
            C[(size_t)m * N + n] = acc[i][j] + bias[n];
        }
    }
}

// ---------------- smem layout (floats) ----------------
#define SM_U    0                        // 12 * 520  U column slices
#define SM_UW   (SM_U   + 12 * 520)      // 12 * 520  Uw column slices
#define SM_UA   (SM_UW  + 12 * 520)     //  4 * 520  Ua column slices
#define SM_HS   (SM_UA  + 4 * 520)      //  4 * 512  active-word h states
#define SM_CS   (SM_HS  + 4 * 512)      //  4 * 512  active-word c states
#define SM_CW   (SM_CS  + 4 * 512)      //  4 * 512  full c_w rows
#define SM_HP   (SM_CW  + 4 * 512)      //  512      h_prev
#define SM_RA   (SM_HP  + 512)          //  48       phase-A dot results
#define SM_RB   (SM_RA  + 48)           //  16       gate dot results (12 used)
#define SM_RAL  (SM_RB  + 16)           //  16       alpha dot results
#define SM_BXW  (SM_RAL + 16)           //  16       XW biases (12 used)
#define SM_BXA  (SM_BXW + 16)           //  16       XWa biases (4 used)
#define SM_BGW  (SM_BXA + 16)           //  48       GWx biases
#define SM_META (SM_BGW + 48)           //  4096     meta table (as uint)
#define SM_TOTF (SM_META + 4096)
#define SMEM_BYTES (SM_TOTF * 4)

// warp dot: length-512, smem x smem, result on lane 0
__device__ __forceinline__ float dot512(const float* wt, const float* hv, int lane) {
    const float4* a4 = (const float4*)wt;
    const float4* b4 = (const float4*)hv;
    float acc = 0.0f;
    #pragma unroll
    for (int i = 0; i < 4; ++i) {
        float4 a = a4[i * 32 + lane];
        float4 b = b4[i * 32 + lane];
        acc += a.x * b.x + a.y * b.y + a.z * b.z + a.w * b.w;
    }
    #pragma unroll
    for (int o = 16; o > 0; o >>= 1)
        acc += __shfl_xor_sync(0xFFFFFFFFu, acc, o);
    return acc;
}

__global__ __launch_bounds__(NT, 1) void k_seq(
    float* __restrict__ out,                 // [T, 1024] = hidden|cell
    const float* __restrict__ U,             // [512, 1536]
    const float* __restrict__ Uw,            // [512, 1536]
    const float* __restrict__ Ua,            // [512, 512]
    const float* __restrict__ h0,
    const float* __restrict__ c0)
{
    extern __shared__ float sm[];
    unsigned* s_meta = (unsigned*)(sm + SM_META);
    const int c     = blockIdx.x;
    const int tid   = threadIdx.x;
    const int jbase = 4 * c;
    const int warp  = tid >> 5, lane = tid & 31;

    // ---- one-time: weight column slices + meta table into smem ----
    for (int idx = tid; idx < 3 * 512; idx += NT) {
        int gate = idx >> 9, k = idx & 511;
        float4 vU  = *(const float4*)(U  + (size_t)k * H3_ + gate * 512 + jbase);
        float4 vUw = *(const float4*)(Uw + (size_t)k * H3_ + gate * 512 + jbase);
        int b = gate * 4;
        sm[SM_U  + (b + 0) * 520 + k] = vU.x;  sm[SM_U  + (b + 1) * 520 + k] = vU.y;
        sm[SM_U  + (b + 2) * 520 + k] = vU.z;  sm[SM_U  + (b + 3) * 520 + k] = vU.w;
        sm[SM_UW + (b + 0) * 520 + k] = vUw.x; sm[SM_UW + (b + 1) * 520 + k] = vUw.y;
        sm[SM_UW + (b + 2) * 520 + k] = vUw.z; sm[SM_UW + (b + 3) * 520 + k] = vUw.w;
    }
    for (int k = tid; k < 512; k += NT) {
        float4 v = *(const float4*)(Ua + (size_t)k * H_ + jbase);
        sm[SM_UA + 0 * 520 + k] = v.x; sm[SM_UA + 1 * 520 + k] = v.y;
        sm[SM_UA + 2 * 520 + k] = v.z; sm[SM_UA + 3 * 520 + k] = v.w;
    }
    for (int i = tid; i < T_; i += NT) s_meta[i] = g_meta[i];
    __syncthreads();

    unsigned seq = 0;
    unsigned* myflag = &g_flag[c * 32];

    for (int t = 0; t < T_; ++t) {
        const unsigned meta = s_meta[t];
        const int nact = (int)(meta & 7u);

        // ---- staging: h_prev, h_s/c_s, precomputed bias scalars ----
        {
            const float* src = t ? (out + (size_t)(t - 1) * 1024) : h0;
            if (tid < 128)
                ((float4*)(sm + SM_HP))[tid] = ((const float4*)src)[tid];
        }
        if (tid < 12)
            sm[SM_BXW + tid] = g_XW[(size_t)t * H3_ + (tid >> 2) * 512 + jbase + (tid & 3)];
        else if (tid >= 16 && tid < 20)
            sm[SM_BXA + (tid - 16)] = g_XWa[(size_t)t * H_ + jbase + (tid - 16)];
        else if (tid >= 32 && tid < 32 + nact * 12) {
            int q = tid - 32, wi = q / 12, g = q % 12;
            int w = (int)((meta >> (3 + 7 * wi)) & 3u);
            sm[SM_BGW + q] =
                g_GWx[((size_t)t * WN_ + w) * H3_ + (g >> 2) * 512 + jbase + (g & 3)];
        }
        if (nact) {
            for (int q = tid; q < nact * 128; q += NT) {
                int wi = q >> 7, k4 = q & 127;
                int slot = (int)((meta >> (3 + 7 * wi)) & 127u);
                int s = t - (slot >> 2);
                const float4* src = (const float4*)(out + (size_t)s * 1024);
                ((float4*)(sm + SM_HS + wi * 512))[k4] = src[k4];
                ((float4*)(sm + SM_CS + wi * 512))[k4] = src[128 + k4];
            }
        }
        __syncthreads();

        if (nact) {
            // ---- phase A: word-gate dots (Uw . h_s) ----
            int ndots = nact * 12;
            for (int d = warp; d < ndots; d += 8) {
                int wi = d / 12, g = d % 12;
                float acc = dot512(sm + SM_UW + g * 520, sm + SM_HS + wi * 512, lane);
                if (lane == 0) sm[SM_RA + d] = acc + sm[SM_BGW + d];
            }
            __syncthreads();
            // ---- c_w for own columns -> publish ----
            if (tid < nact * 4) {
                int wi = tid >> 2, jl = tid & 3;
                float f  = sm[SM_RA + wi * 12 + 0 + jl];
                float iw = sm[SM_RA + wi * 12 + 4 + jl];
                float gw = sm[SM_RA + wi * 12 + 8 + jl];
                float cs = sm[SM_CS + wi * 512 + jbase + jl];
                float sf = 1.0f / (1.0f + expf(-f));
                float si = 1.0f / (1.0f + expf(-iw));
                g_cw[wi * H_ + jbase + jl] = sf * cs + si * tanhf(gw);
            }
            // barrier A arrive
            ++seq;
            __syncthreads();
            if (tid == 0) st_rel(myflag, seq);
            // ---- overlap: main gate dots (U . h_prev), independent of c_w ----
            for (int d = warp; d < 12; d += 8) {
                float acc = dot512(sm + SM_U + d * 520, sm + SM_HP, lane);
                if (lane == 0) sm[SM_RB + d] = acc + sm[SM_BXW + d];
            }
            // barrier A wait
            if (tid < GC) { while (ld_acq(&g_flag[tid * 32]) < seq) {} }
            __syncthreads();
            // ---- stage full c_w (L2-fresh: rewritten every step) ----
            for (int q = tid; q < nact * 128; q += NT)
                ((float4*)(sm + SM_CW))[q] = __ldcv(((const float4*)g_cw) + q);
            __syncthreads();
            // ---- alpha dots (Ua . c_w) ----
            for (int d = warp; d < nact * 4; d += 8) {
                int wi = d >> 2, jl = d & 3;
                float acc = dot512(sm + SM_UA + jl * 520, sm + SM_CW + wi * 512, lane);
                if (lane == 0) sm[SM_RAL + d] = acc + sm[SM_BXA + jl];
            }
            __syncthreads();
        } else {
            // ---- main gate dots only ----
            for (int d = warp; d < 12; d += 8) {
                float acc = dot512(sm + SM_U + d * 520, sm + SM_HP, lane);
                if (lane == 0) sm[SM_RB + d] = acc + sm[SM_BXW + d];
            }
            __syncthreads();
        }

        // ---- final combine ----
        if (tid < 4) {
            int jl = tid, j = jbase + jl;
            float ig = 1.0f / (1.0f + expf(-sm[SM_RB + 0 + jl]));
            float og = 1.0f / (1.0f + expf(-sm[SM_RB + 4 + jl]));
            float gg = tanhf(sm[SM_RB + 8 + jl]);
            float c1;
            if (nact) {
                float e0  = expf(ig);
                float den = e0, num = e0 * gg;
                for (int wi = 0; wi < nact; ++wi) {
                    float a  = 1.0f / (1.0f + expf(-sm[SM_RAL + wi * 4 + jl]));
                    float ea = expf(a);
                    den += ea;
                    num += ea * sm[SM_CW + wi * 512 + j];
                }
                c1 = num / den;
            } else {
                float cp = t ? out[(size_t)(t - 1) * 1024 + 512 + j] : c0[j];
                c1 = (1.0f - ig) * cp + ig * gg;
            }
            float h1 = og * tanhf(c1);
            out[(size_t)t * 1024 + j]       = h1;
            out[(size_t)t * 1024 + 512 + j] = c1;
        }
        // barrier B: publish h_t, c_t
        ++seq;
        __syncthreads();
        if (tid == 0) st_rel(myflag, seq);
        if (tid < GC) { while (ld_acq(&g_flag[tid * 32]) < seq) {} }
        __syncthreads();
    }
}

// ---------------- launch ----------------
extern "C" void kernel_launch(void* const* d_in, const int* in_sizes, int n_in,
                              void* d_out, int out_size) {
    const float* x        = (const float*)d_in[0];
    const int*   word_ids = (const int*)  d_in[1];
    const int*   wstarts  = (const int*)  d_in[2];
    const void*  wmask    = (const void*) d_in[3];
    const float* h0       = (const float*)d_in[4];
    const float* c0       = (const float*)d_in[5];
    const float* emb      = (const float*)d_in[6];
    const float* W        = (const float*)d_in[7];
    const float* U        = (const float*)d_in[8];
    const float* b        = (const float*)d_in[9];
    const float* Wa       = (const float*)d_in[10];
    const float* Ua       = (const float*)d_in[11];
    const float* ba       = (const float*)d_in[12];
    const float* Ww       = (const float*)d_in[13];
    const float* Uw       = (const float*)d_in[14];
    const float* bw       = (const float*)d_in[15];
    float* out = (float*)d_out;

    k_init<<<1, 256>>>();
    k_detect<<<16, 256>>>((const unsigned*)wmask);
    k_meta<<<16, 256>>>(wmask, wstarts);

    {
        dim3 g0(H3_ / 64, T_ / 128);
        k_gemm<<<g0, 256>>>(x, nullptr, W, b, T_, H3_, D_, 0);
        dim3 g1(H_ / 64, T_ / 128);
        k_gemm<<<g1, 256>>>(x, nullptr, Wa, ba, T_, H_, D_, 1);
        dim3 g2(H3_ / 64, (T_ * WN_) / 128);
        k_gemm<<<g2, 256>>>(emb, word_ids, Ww, bw, T_ * WN_, H3_, E_, 2);
    }

    static_assert(SMEM_BYTES < 220 * 1024, "smem");
    cudaFuncSetAttribute(k_seq, cudaFuncAttributeMaxDynamicSharedMemorySize,
                         SMEM_BYTES);
    k_seq<<<GC, NT, SMEM_BYTES>>>(out, U, Uw, Ua, h0, c0);
}